// round 2
// baseline (speedup 1.0000x reference)
#include <cuda_runtime.h>

// AggregationNonCupy: out[n, g*32+cw, oh, ow] =
//   sum_{i,j} weight[n, cw, i*3+j, oh*64+ow] * x_pad[n, g*32+cw, oh+i-1, ow+j-1]
//
// N=16, C=512, H=W=64, C_W=32, groups=16, K=3, pad=1, stride=1, out 64x64.

#define GROUPS   16
#define C_W      32
#define HW       64
#define BDY      8            // threads in y
#define ROWS_PT  2            // output rows per thread
#define TILE_H   (BDY * ROWS_PT)   // 16
#define HALO_W   66
#define HALO_H   (TILE_H + 2)      // 18
#define NTHREADS (HW * BDY)        // 512

__global__ __launch_bounds__(NTHREADS)
void aggregation_kernel(const float* __restrict__ input,
                        const float* __restrict__ weight,
                        float* __restrict__ out)
{
    __shared__ float tile[HALO_H][HALO_W];

    const int tx  = threadIdx.x;          // ow: 0..63
    const int ty  = threadIdx.y;          // 0..7
    const int tid = ty * HW + tx;

    const int htile = blockIdx.x;         // 0..3
    const int cw    = blockIdx.y;         // 0..31
    const int n     = blockIdx.z;         // 0..15

    const int oh0 = htile * TILE_H;
    const int ow  = tx;
    const size_t img_stride = (size_t)HW * HW;  // 4096

    // ---- per-pixel weights into registers (reused across all 16 groups)
    // weight layout: [n][cw][9][4096]
    float wr[ROWS_PT][9];
#pragma unroll
    for (int r = 0; r < ROWS_PT; ++r) {
        const int oh = oh0 + ty + r * BDY;
        const float* wbase = weight + ((size_t)(n * C_W + cw) * 9) * img_stride
                                    + oh * HW + ow;
#pragma unroll
        for (int kk = 0; kk < 9; ++kk)
            wr[r][kk] = __ldg(wbase + kk * img_stride);
    }

    for (int g = 0; g < GROUPS; ++g) {
        const int c = g * C_W + cw;
        const float* inp = input + ((size_t)(n * 512 + c)) * img_stride;

        // ---- cooperative staged load of the 18x66 haloed input tile (1188 elems)
#pragma unroll
        for (int idx = tid; idx < HALO_H * HALO_W; idx += NTHREADS) {
            const int r  = idx / HALO_W;
            const int cc = idx - r * HALO_W;
            const int ih = oh0 - 1 + r;
            const int iw = cc - 1;
            float v = 0.0f;
            if ((unsigned)ih < (unsigned)HW && (unsigned)iw < (unsigned)HW)
                v = __ldg(inp + ih * HW + iw);
            tile[r][cc] = v;
        }
        __syncthreads();

        // ---- 3x3 FMA, 2 output rows per thread
        float* outc = out + ((size_t)(n * 512 + c)) * img_stride;
#pragma unroll
        for (int r = 0; r < ROWS_PT; ++r) {
            const int oty = ty + r * BDY;     // row within tile
            float acc = 0.0f;
#pragma unroll
            for (int i = 0; i < 3; ++i)
#pragma unroll
                for (int j = 0; j < 3; ++j)
                    acc = fmaf(wr[r][i * 3 + j], tile[oty + i][tx + j], acc);
            outc[(oh0 + oty) * HW + ow] = acc;
        }

        __syncthreads();   // smem reuse fence before next group's fill
    }
}

extern "C" void kernel_launch(void* const* d_in, const int* in_sizes, int n_in,
                              void* d_out, int out_size)
{
    const float* input  = (const float*)d_in[0];  // (16, 512, 64, 64) f32
    const float* weight = (const float*)d_in[1];  // (16, 32, 9, 4096) f32
    float* out = (float*)d_out;                   // (16, 512, 64, 64) f32

    dim3 block(HW, BDY, 1);                       // 512 threads
    dim3 grid(HW / TILE_H, C_W, 16);              // 4 x 32 x 16 = 2048 blocks
    aggregation_kernel<<<grid, block>>>(input, weight, out);
}

// round 3
// speedup vs baseline: 1.9828x; 1.9828x over previous
#include <cuda_runtime.h>

// AggregationNonCupy: out[n, g*32+cw, oh, ow] =
//   sum_{i,j} weight[n, cw, i*3+j, oh*64+ow] * x_pad[n, g*32+cw, oh+i-1, ow+j-1]
// N=16, C=512, H=W=64, C_W=32, groups=16, K=3, pad=1, stride=1.
//
// Key facts exploited:
//  * pad=1 with a full-width tile => left/right halo columns are ALWAYS zero
//    -> written once, per-group fill is pure aligned float4 rows.
//  * weight[n,cw,k,pix] is shared by all 16 groups -> registers, loaded once.
//  * double-buffered smem: prefetch g+1 (LDG.128 into regs) overlaps compute of g.

#define GROUPS   16
#define C_W      32
#define HW       64
#define BDY      8                  // threads in y
#define ROWS_PT  2                  // output rows per thread
#define TILE_H   (BDY * ROWS_PT)    // 16
#define HALO_H   (TILE_H + 2)       // 18
#define ROW_F    72                 // smem row stride in floats (4 + 64 + 4)
#define DATA_OFF 4                  // data columns live at [4, 68); zeros at 3 and 68
#define NTHREADS (HW * BDY)         // 512
#define NLOAD    (HALO_H * (HW/4))  // 288 float4 loads per tile

__global__ __launch_bounds__(NTHREADS)
void aggregation_kernel(const float* __restrict__ input,
                        const float* __restrict__ weight,
                        float* __restrict__ out)
{
    __shared__ float tile[2][HALO_H][ROW_F];

    const int tx  = threadIdx.x;          // ow: 0..63
    const int ty  = threadIdx.y;          // 0..7
    const int tid = ty * HW + tx;

    const int htile = blockIdx.x;         // 0..3
    const int cw    = blockIdx.y;         // 0..31
    const int n     = blockIdx.z;         // 0..15

    const int oh0 = htile * TILE_H;
    const size_t img_stride = (size_t)HW * HW;  // 4096

    // ---- zero the constant side-halo columns (cols 3 and 68), both buffers, once
    if (tid < 2 * HALO_H) {
        const int b = tid / HALO_H;
        const int r = tid - b * HALO_H;
        tile[b][r][DATA_OFF - 1]  = 0.0f;
        tile[b][r][DATA_OFF + HW] = 0.0f;
    }

    // ---- per-pixel weights into registers (reused across all 16 groups)
    float wr[ROWS_PT][9];
#pragma unroll
    for (int r = 0; r < ROWS_PT; ++r) {
        const int oh = oh0 + ty + r * BDY;
        const float* wbase = weight + ((size_t)(n * C_W + cw) * 9) * img_stride
                                    + oh * HW + tx;
#pragma unroll
        for (int kk = 0; kk < 9; ++kk)
            wr[r][kk] = __ldg(wbase + kk * img_stride);
    }

    // ---- loader role: threads 0..287 each own one float4 of the haloed tile
    const bool loader = (tid < NLOAD);
    const int  lrow   = tid >> 4;          // 0..17
    const int  lc4    = (tid & 15) << 2;   // 0,4,...,60
    const int  ih     = oh0 - 1 + lrow;    // -1 .. 64
    const bool in_rng = ((unsigned)ih < (unsigned)HW);
    const float* row_ptr = input + ((size_t)n * 512) * img_stride
                                 + (size_t)ih * HW + lc4;   // +c*4096 added per group

    // ---- initial fill: group 0 into buffer 0
    if (loader) {
        float4 v = make_float4(0.f, 0.f, 0.f, 0.f);
        if (in_rng)
            v = *(const float4*)(row_ptr + (size_t)cw * img_stride); // c = cw (g=0)
        *(float4*)&tile[0][lrow][DATA_OFF + lc4] = v;
    }
    __syncthreads();

    int p = 0;
    for (int g = 0; g < GROUPS; ++g) {
        // ---- prefetch group g+1 into registers (overlaps the compute below)
        float4 pf = make_float4(0.f, 0.f, 0.f, 0.f);
        const bool do_pf = loader && (g + 1 < GROUPS);
        if (do_pf && in_rng) {
            const int c_next = (g + 1) * C_W + cw;
            pf = *(const float4*)(row_ptr + (size_t)c_next * img_stride);
        }

        // ---- compute group g from buffer p
        const int c = g * C_W + cw;
        float* outc = out + ((size_t)(n * 512 + c)) * img_stride;
#pragma unroll
        for (int r = 0; r < ROWS_PT; ++r) {
            const int oty = ty + r * BDY;
            float acc = 0.0f;
#pragma unroll
            for (int i = 0; i < 3; ++i)
#pragma unroll
                for (int j = 0; j < 3; ++j)
                    acc = fmaf(wr[r][i * 3 + j],
                               tile[p][oty + i][DATA_OFF + tx - 1 + j], acc);
            outc[(oh0 + oty) * HW + tx] = acc;
        }

        // ---- commit prefetch into the other buffer
        if (do_pf)
            *(float4*)&tile[p ^ 1][lrow][DATA_OFF + lc4] = pf;

        __syncthreads();
        p ^= 1;
    }
}

extern "C" void kernel_launch(void* const* d_in, const int* in_sizes, int n_in,
                              void* d_out, int out_size)
{
    const float* input  = (const float*)d_in[0];  // (16, 512, 64, 64) f32
    const float* weight = (const float*)d_in[1];  // (16, 32, 9, 4096) f32
    float* out = (float*)d_out;                   // (16, 512, 64, 64) f32

    dim3 block(HW, BDY, 1);                       // 512 threads
    dim3 grid(HW / TILE_H, C_W, 16);              // 4 x 32 x 16 = 2048 blocks
    aggregation_kernel<<<grid, block>>>(input, weight, out);
}